// round 6
// baseline (speedup 1.0000x reference)
#include <cuda_runtime.h>
#include <cuda_bf16.h>
#include <cstdint>

// Problem sizes (fixed per reference)
#define BATCH 16384
#define NSETS 1024
#define NCLS  128

// ---------------- device scratch (no allocations allowed) ----------------
__device__ __nv_bfloat16 g_pb[(size_t)BATCH * NSETS];   // clipped p in bf16 (32MB)
__device__ __nv_bfloat16 g_mb[(size_t)NSETS * NSETS];   // moebius in bf16   (2MB)
__device__ float  g_colsum[NSETS];
__device__ double g_acc[3];  // 0: sum log-lik, 1: sum|rowdot-1|, 2: sum relu(-mass)
__device__ int    g_tgt_is64;

// ---------------- PTX helpers ----------------
__device__ __forceinline__ void ldm_x4(uint32_t* r, uint32_t addr) {
    asm volatile("ldmatrix.sync.aligned.m8n8.x4.shared.b16 {%0,%1,%2,%3}, [%4];"
                 : "=r"(r[0]), "=r"(r[1]), "=r"(r[2]), "=r"(r[3]) : "r"(addr));
}
__device__ __forceinline__ void mma16816(float* c, const uint32_t* a, uint32_t b0, uint32_t b1) {
    asm volatile("mma.sync.aligned.m16n8k16.row.col.f32.bf16.bf16.f32 "
                 "{%0,%1,%2,%3}, {%4,%5,%6,%7}, {%8,%9}, {%0,%1,%2,%3};"
                 : "+f"(c[0]), "+f"(c[1]), "+f"(c[2]), "+f"(c[3])
                 : "r"(a[0]), "r"(a[1]), "r"(a[2]), "r"(a[3]), "r"(b0), "r"(b1));
}
#define CP_ASYNC16(sa, ga) \
    asm volatile("cp.async.cg.shared.global [%0], [%1], 16;\n" :: "r"(sa), "l"(ga))
#define CP_COMMIT() asm volatile("cp.async.commit_group;\n" ::: "memory")
#define CP_WAIT1()  asm volatile("cp.async.wait_group 1;\n" ::: "memory")

// ---------------- kernels ----------------
// Detect whether the target-index buffer is int64 or int32.
// Reads the first 128 int32 words (in-bounds under BOTH interpretations:
// int32 buffer = 16384 words, int64 buffer = 32768 words). If the buffer is
// int64, every odd word (high half, little-endian) is exactly 0. If int32,
// odd words are independent uniform samples from [0,128): P(all 64 zero) =
// 128^-64 ~ 0. Deterministic, graph-capturable.
__global__ void detect_tgt(const int* __restrict__ t) {
    int bad = 0;
    #pragma unroll
    for (int i = 0; i < 64; i++) bad |= t[2 * i + 1];
    g_tgt_is64 = (bad == 0) ? 1 : 0;
}

__global__ void init_k() {
    int i = blockIdx.x * 256 + threadIdx.x;
    if (i < NSETS) g_colsum[i] = 0.0f;
    if (i < 3) g_acc[i] = 0.0;
}

// colsum[k] = sum_s M[s,k]; also convert M -> bf16. Grid: 64 blocks x 256 thr.
__global__ void prep_moebius(const float* __restrict__ M) {
    int c = threadIdx.x * 4;
    float4 s = make_float4(0.f, 0.f, 0.f, 0.f);
    int row0 = blockIdx.x * 16;
    #pragma unroll 4
    for (int r = 0; r < 16; r++) {
        int row = row0 + r;
        float4 v = *(const float4*)(M + (size_t)row * NSETS + c);
        s.x += v.x; s.y += v.y; s.z += v.z; s.w += v.w;
        __nv_bfloat162* dst = (__nv_bfloat162*)(g_mb + (size_t)row * NSETS + c);
        dst[0] = __floats2bfloat162_rn(v.x, v.y);
        dst[1] = __floats2bfloat162_rn(v.z, v.w);
    }
    atomicAdd(&g_colsum[c + 0], s.x);
    atomicAdd(&g_colsum[c + 1], s.y);
    atomicAdd(&g_colsum[c + 2], s.z);
    atomicAdd(&g_colsum[c + 3], s.w);
}

// Per-row: clip p, BCE terms (single-log form: t in {0,1} exactly, so
// t*log(p)+(1-t)*log(1-p) == log(t ? p : 1-p)), rowdot with colsum, p->bf16.
// Grid: 2048 blocks x 256 thr; warp w handles row blockIdx.x*8 + w.
__global__ __launch_bounds__(256) void bce_ms_pconv(const float* __restrict__ pred,
                                                    const float* __restrict__ memb,
                                                    const void* __restrict__ tgt) {
    int warp = threadIdx.x >> 5, lane = threadIdx.x & 31;
    int row = blockIdx.x * 8 + warp;
    const float4* pr = (const float4*)(pred + (size_t)row * NSETS);
    int cls;
    if (g_tgt_is64) cls = (int)((const long long*)tgt)[row];
    else            cls = ((const int*)tgt)[row];
    cls = min(max(cls, 0), NCLS - 1);   // defensive: wrong -> rel_err, not crash
    const float4* mr = (const float4*)(memb + (size_t)cls * NSETS);
    const float4* cs = (const float4*)g_colsum;

    float bce = 0.f, dot = 0.f;
    #pragma unroll
    for (int it = 0; it < 8; it++) {
        int i = it * 32 + lane;           // float4 index, 0..255
        float4 p = pr[i];
        float4 m = mr[i];
        float4 c = cs[i];
        p.x = fminf(fmaxf(p.x, 1e-7f), 0.9999999f);
        p.y = fminf(fmaxf(p.y, 1e-7f), 0.9999999f);
        p.z = fminf(fmaxf(p.z, 1e-7f), 0.9999999f);
        p.w = fminf(fmaxf(p.w, 1e-7f), 0.9999999f);
        // t in {0,1}: one log per element; 1-p exact by Sterbenz for p>=0.5
        bce += __logf(m.x > 0.5f ? p.x : 1.f - p.x);
        bce += __logf(m.y > 0.5f ? p.y : 1.f - p.y);
        bce += __logf(m.z > 0.5f ? p.z : 1.f - p.z);
        bce += __logf(m.w > 0.5f ? p.w : 1.f - p.w);
        dot += p.x * c.x + p.y * c.y + p.z * c.z + p.w * c.w;
        __nv_bfloat162* dst = (__nv_bfloat162*)(g_pb + (size_t)row * NSETS + (size_t)i * 4);
        dst[0] = __floats2bfloat162_rn(p.x, p.y);
        dst[1] = __floats2bfloat162_rn(p.z, p.w);
    }
    #pragma unroll
    for (int off = 16; off > 0; off >>= 1) {
        bce += __shfl_down_sync(0xffffffffu, bce, off);
        dot += __shfl_down_sync(0xffffffffu, dot, off);
    }
    __shared__ float s_b[8], s_m[8];
    if (lane == 0) { s_b[warp] = bce; s_m[warp] = fabsf(dot - 1.0f); }
    __syncthreads();
    if (threadIdx.x == 0) {
        float b = 0.f, ms = 0.f;
        #pragma unroll
        for (int i = 0; i < 8; i++) { b += s_b[i]; ms += s_m[i]; }
        atomicAdd(&g_acc[0], (double)b);
        atomicAdd(&g_acc[1], (double)ms);
    }
}

// GEMM: masses[b,s] = sum_k pb[b,k] * mb[s,k]  (both K-major, NT)
// Tile 128x64x32, 256 threads, 8 warps (4x2), warp tile 32x32.
// Grid mapping: blockIdx.x = N tile (16), blockIdx.y = M tile (128) so that a
// concurrent wave covers ALL N-tiles over few M-tiles -> A tiles hit L2 16x.
// Epilogue: sum relu(-acc) -> one atomic per block. Masses never hit memory.
#define BM 128
#define BN 64
#define BK 32
#define LDA 40   // smem row stride in bf16 (32 + 8 pad = 80B, conflict-free & 16B aligned)
#define KT  (NSETS / BK)

__global__ __launch_bounds__(256) void gemm_mr() {
    __shared__ __nv_bfloat16 As[2][BM * LDA];
    __shared__ __nv_bfloat16 Bs[2][BN * LDA];
    int tid = threadIdx.x;
    int warp = tid >> 5, lane = tid & 31;
    int wm = (warp >> 1) * 32;   // warp M offset
    int wn = (warp & 1) * 32;    // warp N offset

    const __nv_bfloat16* Ag = g_pb + (size_t)blockIdx.y * BM * NSETS;
    const __nv_bfloat16* Bg = g_mb + (size_t)blockIdx.x * BN * NSETS;

    int ld_r = tid >> 2;           // 0..63
    int ld_c = (tid & 3) * 8;      // 0,8,16,24

    uint32_t sA0 = (uint32_t)__cvta_generic_to_shared(&As[0][0]);
    uint32_t sA1 = (uint32_t)__cvta_generic_to_shared(&As[1][0]);
    uint32_t sB0 = (uint32_t)__cvta_generic_to_shared(&Bs[0][0]);
    uint32_t sB1 = (uint32_t)__cvta_generic_to_shared(&Bs[1][0]);

    auto load_stage = [&](int st, int kt) {
        int k0 = kt * BK;
        uint32_t sA = st ? sA1 : sA0;
        uint32_t sB = st ? sB1 : sB0;
        CP_ASYNC16(sA + (uint32_t)(ld_r * LDA + ld_c) * 2,
                   Ag + (size_t)ld_r * NSETS + k0 + ld_c);
        CP_ASYNC16(sA + (uint32_t)((ld_r + 64) * LDA + ld_c) * 2,
                   Ag + (size_t)(ld_r + 64) * NSETS + k0 + ld_c);
        CP_ASYNC16(sB + (uint32_t)(ld_r * LDA + ld_c) * 2,
                   Bg + (size_t)ld_r * NSETS + k0 + ld_c);
    };

    float acc[2][4][4];
    #pragma unroll
    for (int i = 0; i < 2; i++)
        #pragma unroll
        for (int j = 0; j < 4; j++)
            #pragma unroll
            for (int k = 0; k < 4; k++) acc[i][j][k] = 0.f;

    load_stage(0, 0);
    CP_COMMIT();

    for (int kt = 0; kt < KT; kt++) {
        if (kt + 1 < KT) load_stage((kt + 1) & 1, kt + 1);
        CP_COMMIT();
        CP_WAIT1();
        __syncthreads();

        int st = kt & 1;
        uint32_t sA = st ? sA1 : sA0;
        uint32_t sB = st ? sB1 : sB0;
        #pragma unroll
        for (int ks = 0; ks < 2; ks++) {
            int kk = ks * 16;
            uint32_t a[2][4], b[2][4];
            #pragma unroll
            for (int mt = 0; mt < 2; mt++) {
                int r = wm + mt * 16 + (lane & 15);
                int c = kk + (lane >> 4) * 8;
                ldm_x4(a[mt], sA + (uint32_t)(r * LDA + c) * 2);
            }
            #pragma unroll
            for (int bt = 0; bt < 2; bt++) {
                int r = wn + bt * 16 + (lane & 15);
                int c = kk + (lane >> 4) * 8;
                ldm_x4(b[bt], sB + (uint32_t)(r * LDA + c) * 2);
            }
            #pragma unroll
            for (int mt = 0; mt < 2; mt++) {
                mma16816(acc[mt][0], a[mt], b[0][0], b[0][2]);
                mma16816(acc[mt][1], a[mt], b[0][1], b[0][3]);
                mma16816(acc[mt][2], a[mt], b[1][0], b[1][2]);
                mma16816(acc[mt][3], a[mt], b[1][1], b[1][3]);
            }
        }
        __syncthreads();
    }

    // Epilogue: sum relu(-mass) over this block's 128x64 tile (layout-agnostic:
    // every product lands in exactly one acc slot, so the plain sum is exact).
    float part = 0.f;
    #pragma unroll
    for (int i = 0; i < 2; i++)
        #pragma unroll
        for (int j = 0; j < 4; j++)
            #pragma unroll
            for (int k = 0; k < 4; k++) part += fmaxf(-acc[i][j][k], 0.f);
    #pragma unroll
    for (int off = 16; off > 0; off >>= 1)
        part += __shfl_down_sync(0xffffffffu, part, off);
    __shared__ float sp[8];
    if (lane == 0) sp[warp] = part;
    __syncthreads();
    if (tid == 0) {
        float s = 0.f;
        #pragma unroll
        for (int i = 0; i < 8; i++) s += sp[i];
        atomicAdd(&g_acc[2], (double)s);
    }
}

__global__ void finalize_k(float* out, int out_size) {
    double inv_bs = 1.0 / ((double)BATCH * (double)NSETS);
    double bce = -g_acc[0] * inv_bs;
    double ms  = g_acc[1] / (double)BATCH;
    double mr  = g_acc[2] * inv_bs;
    float vals[4];
    vals[0] = (float)(bce + 0.001 * mr + 0.001 * ms);
    vals[1] = (float)bce;
    vals[2] = (float)mr;
    vals[3] = (float)ms;
    for (int i = 0; i < 4 && i < out_size; i++) out[i] = vals[i];
}

// ---------------- launch ----------------
extern "C" void kernel_launch(void* const* d_in, const int* in_sizes, int n_in,
                              void* d_out, int out_size) {
    // Identify inputs by element count (robust to metadata ordering)
    const float* pred = nullptr;       // 16384*1024
    const float* memb = nullptr;       // 128*1024
    const float* moeb = nullptr;       // 1024*1024
    const void*  tgt  = nullptr;       // 16384 (int32 OR int64 — detected on device)
    for (int i = 0; i < n_in; i++) {
        long long n = in_sizes[i];
        if (n == (long long)BATCH * NSETS) pred = (const float*)d_in[i];
        else if (n == (long long)NCLS * NSETS) memb = (const float*)d_in[i];
        else if (n == (long long)NSETS * NSETS) moeb = (const float*)d_in[i];
        else if (n == (long long)BATCH) tgt = d_in[i];
    }
    if (!pred || !memb || !moeb || !tgt) return;

    detect_tgt<<<1, 1>>>((const int*)tgt);
    init_k<<<4, 256>>>();
    prep_moebius<<<64, 256>>>(moeb);
    bce_ms_pconv<<<BATCH / 8, 256>>>(pred, memb, tgt);
    dim3 g(NSETS / BN, BATCH / BM);   // x = N tiles (16), y = M tiles (128)
    gemm_mr<<<g, 256>>>();
    finalize_k<<<1, 1>>>((float*)d_out, out_size);
}